// round 2
// baseline (speedup 1.0000x reference)
#include <cuda_runtime.h>
#include <math.h>

// Problem constants
#define B_   8
#define T_   4
#define C_   512
#define H_   32
#define W_   32
#define HW_  1024
#define BT_  32          // B_*T_
#define TC_  2048        // T_*C_
#define KSPLIT 8
#define CPB  (C_/KSPLIT) // 64 channels per block
#define HP_  28
#define WP_  28
#define NP_  784         // 28*28
#define BN_EPS 1e-5
#define BSTRIDE ((size_t)T_ * C_ * HW_)   // elements between consecutive b

// Scratch (allocation-free rule: __device__ globals)
__device__ float g_A[TC_];
__device__ float g_B[TC_];
__device__ float g_D[TC_];
__device__ float g_part[KSPLIT][BT_ * HW_];

// ---------------------------------------------------------------------------
// Kernel 1: per-(t,c) stats for left and right -> A, B, D coefficients.
// grid: 2048 blocks (tc), 256 threads. Loads are explicitly front-batched
// (8 independent float4 per tensor) for MLP; reduction is warp-shuffle float
// + tiny double combine (short tail, 1 syncthreads).
// ---------------------------------------------------------------------------
__global__ __launch_bounds__(256) void stats_kernel(
    const float* __restrict__ l, const float* __restrict__ r,
    const float* __restrict__ gamma)
{
    const int tc  = blockIdx.x;      // t*C + c
    const int t   = tc >> 9;
    const int c   = tc & (C_ - 1);
    const int tid = threadIdx.x;

    const size_t base = ((size_t)(t * C_ + c)) * HW_ + (size_t)tid * 4;

    float sl = 0.f, ql = 0.f, sr = 0.f, qr = 0.f;
    {
        float4 v[B_];
        #pragma unroll
        for (int b = 0; b < B_; b++)
            v[b] = *reinterpret_cast<const float4*>(l + base + (size_t)b * BSTRIDE);
        #pragma unroll
        for (int b = 0; b < B_; b++) {
            sl += v[b].x + v[b].y + v[b].z + v[b].w;
            ql = fmaf(v[b].x, v[b].x, ql);
            ql = fmaf(v[b].y, v[b].y, ql);
            ql = fmaf(v[b].z, v[b].z, ql);
            ql = fmaf(v[b].w, v[b].w, ql);
        }
        #pragma unroll
        for (int b = 0; b < B_; b++)
            v[b] = *reinterpret_cast<const float4*>(r + base + (size_t)b * BSTRIDE);
        #pragma unroll
        for (int b = 0; b < B_; b++) {
            sr += v[b].x + v[b].y + v[b].z + v[b].w;
            qr = fmaf(v[b].x, v[b].x, qr);
            qr = fmaf(v[b].y, v[b].y, qr);
            qr = fmaf(v[b].z, v[b].z, qr);
            qr = fmaf(v[b].w, v[b].w, qr);
        }
    }

    // warp-level float reduction
    #pragma unroll
    for (int o = 16; o > 0; o >>= 1) {
        sl += __shfl_xor_sync(0xffffffffu, sl, o);
        ql += __shfl_xor_sync(0xffffffffu, ql, o);
        sr += __shfl_xor_sync(0xffffffffu, sr, o);
        qr += __shfl_xor_sync(0xffffffffu, qr, o);
    }

    __shared__ float w0[8], w1[8], w2[8], w3[8];
    const int wid  = tid >> 5;
    const int lane = tid & 31;
    if (lane == 0) { w0[wid] = sl; w1[wid] = ql; w2[wid] = sr; w3[wid] = qr; }
    __syncthreads();

    if (tid == 0) {
        double S0 = 0, S1 = 0, S2 = 0, S3 = 0;
        #pragma unroll
        for (int k = 0; k < 8; k++) {
            S0 += (double)w0[k]; S1 += (double)w1[k];
            S2 += (double)w2[k]; S3 += (double)w3[k];
        }
        const double n = (double)(B_ * HW_);   // 8192
        double mul = S0 / n;
        double mur = S2 / n;
        double varl = S1 / n - mul * mul;
        double varr = S3 / n - mur * mur;
        double invl = 1.0 / sqrt(varl + BN_EPS);
        double invr = 1.0 / sqrt(varr + BN_EPS);
        double g = (double)gamma[c];
        double A = g * invl;
        double Bc = g * invr;
        g_A[tc] = (float)A;
        g_B[tc] = (float)Bc;
        g_D[tc] = (float)(A * mul - Bc * mur);
    }
}

// ---------------------------------------------------------------------------
// Kernel 2: diff2 partials. grid: 32 (b,t) x 8 channel-splits, 1024 threads.
// Each thread owns one spatial position, loops 64 channels. Fully coalesced,
// unroll 8 for MLP. Second full pass over the tensors -> substantial L2 hits.
// ---------------------------------------------------------------------------
__global__ __launch_bounds__(1024) void diff2_kernel(
    const float* __restrict__ l, const float* __restrict__ r)
{
    const int bt   = blockIdx.x / KSPLIT;   // b*T + t
    const int part = blockIdx.x % KSPLIT;
    const int hw   = threadIdx.x;           // 0..1023
    const int t    = bt % T_;

    __shared__ float sA[CPB], sB[CPB], sD[CPB];
    if (hw < CPB) {
        int tc = t * C_ + part * CPB + hw;
        sA[hw] = g_A[tc];
        sB[hw] = g_B[tc];
        sD[hw] = g_D[tc];
    }
    __syncthreads();

    const float* lp = l + ((size_t)(bt * C_ + part * CPB)) * HW_ + hw;
    const float* rp = r + ((size_t)(bt * C_ + part * CPB)) * HW_ + hw;

    float acc = 0.f;
    #pragma unroll 8
    for (int i = 0; i < CPB; i++) {
        float d = sA[i] * lp[(size_t)i * HW_] - sB[i] * rp[(size_t)i * HW_] - sD[i];
        acc = fmaf(d, d, acc);
    }
    g_part[part][bt * HW_ + hw] = acc;
}

// ---------------------------------------------------------------------------
// Kernel 3: sum partials, 5x5 window sum, sqrt, max + first-argmin.
// grid: 32 blocks (one per (b,t)), 1024 threads.
// Output layout (all float32, tuple order, row-major flattened):
//   [0,32)         asymmetry_values   (B,T)
//   [32,96)        asymmetry_coords   (B,T,2) as floats, [x, y]
//   [96,25184)     heatmap            (B,T,28,28)
// ---------------------------------------------------------------------------
__global__ __launch_bounds__(1024) void finalize_kernel(float* __restrict__ out)
{
    const int bt  = blockIdx.x;
    const int tid = threadIdx.x;

    __shared__ float d2[HW_];
    {
        float s = 0.f;
        #pragma unroll
        for (int k = 0; k < KSPLIT; k++) s += g_part[k][bt * HW_ + tid];
        d2[tid] = s;
    }
    __syncthreads();

    float mymax = -3.0e38f;
    float mymin =  3.0e38f;
    int   myidx = 0x7fffffff;

    if (tid < NP_) {
        const int y = tid / WP_;
        const int x = tid % WP_;
        float ws = 0.f;
        #pragma unroll
        for (int dy = 0; dy < 5; dy++) {
            #pragma unroll
            for (int dx = 0; dx < 5; dx++) {
                ws += d2[(y + dy) * W_ + (x + dx)];
            }
        }
        float hm = sqrtf(ws / 25.0f);
        out[96 + bt * NP_ + tid] = hm;
        mymax = hm;
        mymin = hm;
        myidx = tid;
    }

    __shared__ float smx[1024];
    __shared__ float smn[1024];
    __shared__ int   six[1024];
    smx[tid] = mymax; smn[tid] = mymin; six[tid] = myidx;
    __syncthreads();
    for (int st = 512; st > 0; st >>= 1) {
        if (tid < st) {
            smx[tid] = fmaxf(smx[tid], smx[tid + st]);
            float v = smn[tid + st];
            int  ix = six[tid + st];
            // first-occurrence argmin (JAX semantics)
            if (v < smn[tid] || (v == smn[tid] && ix < six[tid])) {
                smn[tid] = v; six[tid] = ix;
            }
        }
        __syncthreads();
    }

    if (tid == 0) {
        out[bt] = smx[0];
        int idx = six[0];
        out[32 + bt * 2 + 0] = (float)(idx % WP_);  // x_argmin
        out[32 + bt * 2 + 1] = (float)(idx / WP_);  // y_argmin
    }
}

// ---------------------------------------------------------------------------
extern "C" void kernel_launch(void* const* d_in, const int* in_sizes, int n_in,
                              void* d_out, int out_size)
{
    const float* l     = (const float*)d_in[0];
    const float* r     = (const float*)d_in[1];
    const float* gamma = (const float*)d_in[2];
    // d_in[3] = bn_beta: cancels exactly in (l_bn - r_bn), unused.
    float* out = (float*)d_out;

    stats_kernel<<<TC_, 256>>>(l, r, gamma);
    diff2_kernel<<<BT_ * KSPLIT, 1024>>>(l, r);
    finalize_kernel<<<BT_, 1024>>>(out);
}